// round 2
// baseline (speedup 1.0000x reference)
#include <cuda_runtime.h>
#include <cuda_bf16.h>
#include <math.h>

#define N_QUERIES 8192
#define N_WAY 5
#define DIM 256

// Scratch accumulators (allocation-free: __device__ globals).
__device__ double g_loss_sum;
__device__ int    g_correct;

__global__ void proto_zero_kernel() {
    g_loss_sum = 0.0;
    g_correct  = 0;
}

// One warp per query. Lane l holds q[l*4 .. ] via float4 at indices l and l+32
// (64 float4 per 256-float row). Fully coalesced for both qry and prompt.
__global__ __launch_bounds__(256) void proto_main_kernel(
    const float* __restrict__ qry,      // [N, DIM]
    const float* __restrict__ prompt,   // [N*N_WAY, DIM]
    const float* __restrict__ labels)   // [N, N_WAY] one-hot
{
    const int warp = (blockIdx.x * blockDim.x + threadIdx.x) >> 5;
    const int lane = threadIdx.x & 31;
    if (warp >= N_QUERIES) return;

    const float4* q4 = reinterpret_cast<const float4*>(qry + (size_t)warp * DIM);
    float4 qa = q4[lane];
    float4 qb = q4[lane + 32];

    float dist[N_WAY];
#pragma unroll
    for (int w = 0; w < N_WAY; ++w) {
        const float4* p4 = reinterpret_cast<const float4*>(
            prompt + ((size_t)warp * N_WAY + w) * DIM);
        float4 pa = p4[lane];
        float4 pb = p4[lane + 32];
        float dx, s;
        dx = qa.x - pa.x; s  = dx * dx;
        dx = qa.y - pa.y; s += dx * dx;
        dx = qa.z - pa.z; s += dx * dx;
        dx = qa.w - pa.w; s += dx * dx;
        dx = qb.x - pb.x; s += dx * dx;
        dx = qb.y - pb.y; s += dx * dx;
        dx = qb.z - pb.z; s += dx * dx;
        dx = qb.w - pb.w; s += dx * dx;
        dist[w] = s;
    }

    // Warp-reduce the 5 partial sums.
#pragma unroll
    for (int off = 16; off > 0; off >>= 1) {
#pragma unroll
        for (int w = 0; w < N_WAY; ++w)
            dist[w] += __shfl_xor_sync(0xFFFFFFFFu, dist[w], off);
    }

    if (lane == 0) {
        // logits = -dist; log_softmax over 5.
        // max logit = -min dist; argmax logit = argmin dist (first on ties,
        // matching jnp.argmax semantics via strict <).
        float mind = dist[0];
        int   amin = 0;
#pragma unroll
        for (int w = 1; w < N_WAY; ++w) {
            if (dist[w] < mind) { mind = dist[w]; amin = w; }
        }
        float sumexp = 0.0f;
#pragma unroll
        for (int w = 0; w < N_WAY; ++w)
            sumexp += __expf(mind - dist[w]);   // exp(logit - maxlogit)
        float lse = logf(sumexp);               // log-sum-exp offset

        // One-hot label: first index with value > 0.5 (it is exactly 1.0).
        const float* lbl = labels + (size_t)warp * N_WAY;
        int label = 0;
#pragma unroll
        for (int w = N_WAY - 1; w >= 1; --w)
            if (lbl[w] > 0.5f) label = w;

        // log_prob[label] = -dist[label] - (-mind) - lse
        float logp = (mind - dist[label]) - lse;
        atomicAdd(&g_loss_sum, (double)(-logp));
        if (amin == label) atomicAdd(&g_correct, 1);
    }
}

__global__ void proto_finalize_kernel(float* __restrict__ out) {
    out[0] = (float)(g_loss_sum / (double)N_QUERIES);
    out[1] = (float)g_correct / (float)N_QUERIES;
}

extern "C" void kernel_launch(void* const* d_in, const int* in_sizes, int n_in,
                              void* d_out, int out_size) {
    const float* qry    = (const float*)d_in[0];
    const float* prompt = (const float*)d_in[1];
    const float* labels = (const float*)d_in[2];
    float* out = (float*)d_out;

    proto_zero_kernel<<<1, 1>>>();
    // 8192 warps, 8 warps (256 threads) per block -> 1024 blocks.
    proto_main_kernel<<<N_QUERIES / 8, 256>>>(qry, prompt, labels);
    proto_finalize_kernel<<<1, 1>>>(out);
}

// round 3
// speedup vs baseline: 2.0000x; 2.0000x over previous
#include <cuda_runtime.h>
#include <cuda_bf16.h>
#include <math.h>

#define N_QUERIES 8192
#define N_WAY 5
#define DIM 256
#define WARPS_PER_BLOCK 8
#define GRID_BLOCKS (N_QUERIES / WARPS_PER_BLOCK)   // 1024

// Accumulators. Zero at module load; the last finishing block resets them
// after producing the output, so every graph replay starts from zero.
__device__ double       g_loss_sum = 0.0;
__device__ int          g_correct  = 0;
__device__ unsigned int g_ticket   = 0;

__global__ __launch_bounds__(256) void proto_fused_kernel(
    const float* __restrict__ qry,      // [N, DIM]
    const float* __restrict__ prompt,   // [N*N_WAY, DIM]
    const float* __restrict__ labels,   // [N, N_WAY] one-hot
    float* __restrict__ out)            // [2]: loss, acc
{
    __shared__ float s_loss[WARPS_PER_BLOCK];
    __shared__ int   s_corr[WARPS_PER_BLOCK];

    const int warp_in_blk = threadIdx.x >> 5;
    const int lane        = threadIdx.x & 31;
    const int query       = blockIdx.x * WARPS_PER_BLOCK + warp_in_blk;

    // ---- per-query distance computation (one warp per query) ----
    const float4* q4 = reinterpret_cast<const float4*>(qry + (size_t)query * DIM);
    float4 qa = q4[lane];
    float4 qb = q4[lane + 32];

    float dist[N_WAY];
#pragma unroll
    for (int w = 0; w < N_WAY; ++w) {
        const float4* p4 = reinterpret_cast<const float4*>(
            prompt + ((size_t)query * N_WAY + w) * DIM);
        float4 pa = p4[lane];
        float4 pb = p4[lane + 32];
        float dx, s;
        dx = qa.x - pa.x; s  = dx * dx;
        dx = qa.y - pa.y; s += dx * dx;
        dx = qa.z - pa.z; s += dx * dx;
        dx = qa.w - pa.w; s += dx * dx;
        dx = qb.x - pb.x; s += dx * dx;
        dx = qb.y - pb.y; s += dx * dx;
        dx = qb.z - pb.z; s += dx * dx;
        dx = qb.w - pb.w; s += dx * dx;
        dist[w] = s;
    }

#pragma unroll
    for (int off = 16; off > 0; off >>= 1) {
#pragma unroll
        for (int w = 0; w < N_WAY; ++w)
            dist[w] += __shfl_xor_sync(0xFFFFFFFFu, dist[w], off);
    }

    if (lane == 0) {
        float mind = dist[0];
        int   amin = 0;
#pragma unroll
        for (int w = 1; w < N_WAY; ++w)
            if (dist[w] < mind) { mind = dist[w]; amin = w; }

        float sumexp = 0.0f;
#pragma unroll
        for (int w = 0; w < N_WAY; ++w)
            sumexp += __expf(mind - dist[w]);
        float lse = logf(sumexp);

        const float* lbl = labels + (size_t)query * N_WAY;
        int label = 0;
#pragma unroll
        for (int w = N_WAY - 1; w >= 1; --w)
            if (lbl[w] > 0.5f) label = w;

        float logp = (mind - dist[label]) - lse;   // log_softmax at label
        s_loss[warp_in_blk] = -logp;
        s_corr[warp_in_blk] = (amin == label) ? 1 : 0;
    }
    __syncthreads();

    // ---- block reduce + single atomic per block ----
    if (threadIdx.x == 0) {
        float bl = 0.0f;
        int   bc = 0;
#pragma unroll
        for (int i = 0; i < WARPS_PER_BLOCK; ++i) { bl += s_loss[i]; bc += s_corr[i]; }
        atomicAdd(&g_loss_sum, (double)bl);
        atomicAdd(&g_correct, bc);

        __threadfence();
        unsigned int t = atomicAdd(&g_ticket, 1u);
        if (t == GRID_BLOCKS - 1) {
            // Last block: finalize and reset for the next graph replay.
            out[0] = (float)(g_loss_sum / (double)N_QUERIES);
            out[1] = (float)g_correct / (float)N_QUERIES;
            g_loss_sum = 0.0;
            g_correct  = 0;
            g_ticket   = 0;
        }
    }
}

extern "C" void kernel_launch(void* const* d_in, const int* in_sizes, int n_in,
                              void* d_out, int out_size) {
    const float* qry    = (const float*)d_in[0];
    const float* prompt = (const float*)d_in[1];
    const float* labels = (const float*)d_in[2];
    float* out = (float*)d_out;

    proto_fused_kernel<<<GRID_BLOCKS, 256>>>(qry, prompt, labels, out);
}